// round 4
// baseline (speedup 1.0000x reference)
#include <cuda_runtime.h>
#include <cstdint>

// FM second-order term:
//   out[b] = sum_e (features[b,:] @ W[:,e])^2  -  sum_f features[b,f]^2 * w2sum[f]
// B=16384, F=200, E=64, fp32.
//
// R4: balanced tile. 64-thr block = 8 eg x 4 fs x 2 rg. Thread: 8 rows x
// 8 e-cols x 50 features (fs quarter). 32 f32x2 accumulators -> deep ILP.
// L1-wavefront : FMA-cycle ratio = 4(R+Ec)/(4 R Ec) = 100% (was 150%).
// Features cp.async-staged to smem; fv pipelined via LDS.64; W L1-resident.

typedef unsigned long long ull;

__device__ __forceinline__ ull pack2(float a, float b) {
    ull r; asm("mov.b64 %0, {%1, %2};" : "=l"(r) : "f"(a), "f"(b)); return r;
}
__device__ __forceinline__ void ffma2(ull &d, ull a, ull b) {
    asm("fma.rn.f32x2 %0, %1, %2, %0;" : "+l"(d) : "l"(a), "l"(b));
}
__device__ __forceinline__ ull fmul2(ull a, ull b) {
    ull r; asm("mul.rn.f32x2 %0, %1, %2;" : "=l"(r) : "l"(a), "l"(b)); return r;
}
__device__ __forceinline__ ull fadd2(ull a, ull b) {
    ull r; asm("add.rn.f32x2 %0, %1, %2;" : "=l"(r) : "l"(a), "l"(b)); return r;
}
__device__ __forceinline__ float lohisum(ull v) {
    float lo, hi; asm("mov.b64 {%0, %1}, %2;" : "=f"(lo), "=f"(hi) : "l"(v)); return lo + hi;
}
__device__ __forceinline__ ull shflx(ull v, int m) {
    uint32_t lo = (uint32_t)v, hi = (uint32_t)(v >> 32);
    lo = __shfl_xor_sync(0xffffffffu, lo, m);
    hi = __shfl_xor_sync(0xffffffffu, hi, m);
    return ((ull)hi << 32) | lo;
}
__device__ __forceinline__ uint32_t smem_u32(const void* p) {
    return (uint32_t)__cvta_generic_to_shared(p);
}
__device__ __forceinline__ void cp_async16(uint32_t s, const void* g) {
    asm volatile("cp.async.cg.shared.global [%0], [%1], 16;" :: "r"(s), "l"(g));
}

constexpr int F_DIM = 200;
constexpr int E_DIM = 64;
constexpr int THREADS = 64;
constexpr int RPB = 16;            // rows per block
constexpr int RPT = 8;             // rows per thread
constexpr int NK = 25;             // 2-feature chunks per fs quarter (50 feats)

// compute chunk k (features g0=fbase+2k, g0+1), optionally prefetch fv for k+1
__device__ __forceinline__ void chunk(
    int k, bool pre, const float* __restrict__ fb, const float* __restrict__ Wq,
    int fbase, float2 cur[RPT], float2 nxt[RPT], ull acc[RPT][4])
{
    if (pre) {
        const int kk = (k + 1 < NK) ? k + 1 : 0;
        #pragma unroll
        for (int r = 0; r < RPT; ++r)
            nxt[r] = *(const float2*)(fb + r * F_DIM + 2 * kk);
    }
    const int g0 = fbase + 2 * k;
    ulonglong2 wA0 = *(const ulonglong2*)(Wq + (size_t)g0 * E_DIM);
    ulonglong2 wA1 = *(const ulonglong2*)(Wq + (size_t)g0 * E_DIM + 4);
    ulonglong2 wB0 = *(const ulonglong2*)(Wq + (size_t)(g0 + 1) * E_DIM);
    ulonglong2 wB1 = *(const ulonglong2*)(Wq + (size_t)(g0 + 1) * E_DIM + 4);

    #pragma unroll
    for (int r = 0; r < RPT; ++r) {
        ull p0 = pack2(cur[r].x, cur[r].x);
        ffma2(acc[r][0], p0, wA0.x); ffma2(acc[r][1], p0, wA0.y);
        ffma2(acc[r][2], p0, wA1.x); ffma2(acc[r][3], p0, wA1.y);
        ull p1 = pack2(cur[r].y, cur[r].y);
        ffma2(acc[r][0], p1, wB0.x); ffma2(acc[r][1], p1, wB0.y);
        ffma2(acc[r][2], p1, wB1.x); ffma2(acc[r][3], p1, wB1.y);
    }
}

__global__ void __launch_bounds__(THREADS, 7)
fm_kernel(const float* __restrict__ features,
          const float* __restrict__ W,
          float* __restrict__ out)
{
    __shared__ __align__(16) float fbuf[RPB][F_DIM];   // 12.8 KB
    __shared__ __align__(16) float w2s[F_DIM];         // 800 B

    const int tid  = threadIdx.x;
    const int eg   = tid & 7;          // e-cols eg*8 .. eg*8+7
    const int fs   = (tid >> 3) & 3;   // feature quarter
    const int rg   = tid >> 5;         // warp id = row group
    const int lane = tid & 31;

    // stage 16 feature rows (contiguous 12.8 KB) via cp.async
    {
        const float* src = features + (size_t)blockIdx.x * RPB * F_DIM;
        uint32_t dst = smem_u32(&fbuf[0][0]);
        for (int i = tid; i < RPB * F_DIM / 4; i += THREADS)
            cp_async16(dst + i * 16, src + i * 4);
        asm volatile("cp.async.commit_group;");
    }
    // w2sum[f] = sum_e W[f,e]^2 (L1-warm after first block on each SM)
    for (int f = tid; f < F_DIM; f += THREADS) {
        const float4* wr = (const float4*)(W + (size_t)f * E_DIM);
        float s = 0.f;
        #pragma unroll
        for (int i = 0; i < E_DIM / 4; ++i) {
            float4 v = wr[i];
            s += v.x * v.x + v.y * v.y + v.z * v.z + v.w * v.w;
        }
        w2s[f] = s;
    }
    asm volatile("cp.async.wait_group 0;" ::: "memory");
    __syncthreads();

    const int fbase = fs * 50;                     // this quarter's features
    const float* fb = &fbuf[rg * RPT][0] + fbase;  // row-local feature base
    const float* Wq = W + eg * 8;

    ull acc[RPT][4];
    #pragma unroll
    for (int r = 0; r < RPT; ++r)
        #pragma unroll
        for (int j = 0; j < 4; ++j) acc[r][j] = 0ull;

    float2 fva[RPT], fvb[RPT];
    #pragma unroll
    for (int r = 0; r < RPT; ++r)
        fva[r] = *(const float2*)(fb + r * F_DIM);

    #pragma unroll 1
    for (int k = 0; k < NK - 1; k += 2) {
        chunk(k,     true, fb, Wq, fbase, fva, fvb, acc);
        chunk(k + 1, true, fb, Wq, fbase, fvb, fva, acc);
    }
    chunk(NK - 1, false, fb, Wq, fbase, fva, fvb, acc);

    // squared term: lane handles features lane, lane+32, ... (all 200)
    float sqa[RPT];
    #pragma unroll
    for (int r = 0; r < RPT; ++r) sqa[r] = 0.f;
    #pragma unroll
    for (int k = 0; k < 7; ++k) {
        const int f = lane + 32 * k;
        const bool ok = f < F_DIM;
        const float wv = ok ? w2s[f] : 0.f;
        #pragma unroll
        for (int r = 0; r < RPT; ++r) {
            const float x = ok ? fbuf[rg * RPT + r][f] : 0.f;
            sqa[r] = fmaf(x * x, wv, sqa[r]);
        }
    }

    // finalize per row: fs-reduce accs (xor 8,16), square+sum e, eg+sq reduce
    const int rowbase = blockIdx.x * RPB + rg * RPT;
    #pragma unroll
    for (int r = 0; r < RPT; ++r) {
        ull m0 = acc[r][0], m1 = acc[r][1], m2 = acc[r][2], m3 = acc[r][3];
        m0 = fadd2(m0, shflx(m0, 8));  m1 = fadd2(m1, shflx(m1, 8));
        m2 = fadd2(m2, shflx(m2, 8));  m3 = fadd2(m3, shflx(m3, 8));
        m0 = fadd2(m0, shflx(m0, 16)); m1 = fadd2(m1, shflx(m1, 16));
        m2 = fadd2(m2, shflx(m2, 16)); m3 = fadd2(m3, shflx(m3, 16));
        ull t = fadd2(fadd2(fmul2(m0, m0), fmul2(m1, m1)),
                      fadd2(fmul2(m2, m2), fmul2(m3, m3)));
        float v = (fs == 0) ? lohisum(t) : 0.f;   // fs-replicated: count once
        v -= sqa[r];
        v += __shfl_xor_sync(0xffffffffu, v, 1);
        v += __shfl_xor_sync(0xffffffffu, v, 2);
        v += __shfl_xor_sync(0xffffffffu, v, 4);
        v += __shfl_xor_sync(0xffffffffu, v, 8);
        v += __shfl_xor_sync(0xffffffffu, v, 16);
        if (lane == 0) out[rowbase + r] = v;
    }
}

extern "C" void kernel_launch(void* const* d_in, const int* in_sizes, int n_in,
                              void* d_out, int out_size)
{
    const float* features = (const float*)d_in[0];
    const float* W        = (const float*)d_in[1];
    if (n_in >= 2 && in_sizes[0] < in_sizes[1]) {
        features = (const float*)d_in[1];
        W        = (const float*)d_in[0];
    }
    float* out = (float*)d_out;

    const int B = out_size;            // 16384
    const int blocks = B / RPB;        // 1024 -> single wave at 7/SM
    fm_kernel<<<blocks, THREADS>>>(features, W, out);
}

// round 6
// speedup vs baseline: 1.3902x; 1.3902x over previous
#include <cuda_runtime.h>
#include <cstdint>

// FM second-order term via legacy mma.sync (HMMA) split-bf16 GEMM.
//   sum_emb = features @ W  (M=16384, K=200->208, N=64), 3 bf16 products
//   out[b]  = sum_e sum_emb[b,e]^2 - sum_f features[b,f]^2 * w2sum[f]
// Per CTA: 128-row M-tile. A smem row-major stride 432B (ldmatrix
// conflict-free), B smem k-major stride 144B (ldmatrix.trans). 8 warps =
// 4 m-groups x 2 n-groups, warp tile 32x32, full k-unroll (13 steps).

typedef unsigned long long ull;

constexpr int F_DIM = 200;
constexpr int E_DIM = 64;
constexpr int MTILE = 128;
constexpr int THREADS = 256;
constexpr int NK = 13;                  // 13*16 = 208 >= 200

constexpr int SA_B = 432;               // A row stride (216 bf16)
constexpr int SB_B = 144;               // B row stride (72 bf16)

constexpr int SM_A_HI = 0;              // 128*432 = 55296
constexpr int SM_A_LO = 55296;
constexpr int SM_B_HI = 110592;         // 208*144 = 29952
constexpr int SM_B_LO = 140544;
constexpr int SM_W2S  = 170496;         // 200*4
constexpr int SM_SQS  = 171296;         // 128*4
constexpr int SM_PART = 171808;         // 2*128*4
constexpr int SMEM_TOTAL = 172832;

__device__ __forceinline__ uint32_t smem_u32(const void* p) {
    return (uint32_t)__cvta_generic_to_shared(p);
}
__device__ __forceinline__ uint32_t cvt_bf16x2(float lo, float hi) {
    uint32_t r;  // r = {bits0..15 = bf16(lo), bits16..31 = bf16(hi)}
    asm("cvt.rn.bf16x2.f32 %0, %1, %2;" : "=r"(r) : "f"(hi), "f"(lo));
    return r;
}
__device__ __forceinline__ void ldm_x4(uint32_t* r, uint32_t a) {
    asm volatile("ldmatrix.sync.aligned.m8n8.x4.shared.b16 {%0,%1,%2,%3}, [%4];"
                 : "=r"(r[0]), "=r"(r[1]), "=r"(r[2]), "=r"(r[3]) : "r"(a));
}
__device__ __forceinline__ void ldm_x4_t(uint32_t* r, uint32_t a) {
    asm volatile("ldmatrix.sync.aligned.m8n8.x4.trans.shared.b16 {%0,%1,%2,%3}, [%4];"
                 : "=r"(r[0]), "=r"(r[1]), "=r"(r[2]), "=r"(r[3]) : "r"(a));
}
__device__ __forceinline__ void mma_bf16(float* c, const uint32_t* a,
                                         uint32_t b0, uint32_t b1) {
    asm volatile(
        "mma.sync.aligned.m16n8k16.row.col.f32.bf16.bf16.f32 "
        "{%0,%1,%2,%3}, {%4,%5,%6,%7}, {%8,%9}, {%0,%1,%2,%3};"
        : "+f"(c[0]), "+f"(c[1]), "+f"(c[2]), "+f"(c[3])
        : "r"(a[0]), "r"(a[1]), "r"(a[2]), "r"(a[3]), "r"(b0), "r"(b1));
}

__global__ void __launch_bounds__(THREADS, 1)
fm_mma_kernel(const float* __restrict__ features,
              const float* __restrict__ W,
              float* __restrict__ out)
{
    extern __shared__ __align__(16) char smem[];
    const uint32_t sb = smem_u32(smem);
    const int tid  = threadIdx.x;
    const int w    = tid >> 5;
    const int lane = tid & 31;
    const int mg   = w >> 1;            // m-group 0..3 (rows 32*mg..)
    const int ng   = w & 1;             // n-group 0..1 (cols 32*ng..)

    float* w2s  = (float*)(smem + SM_W2S);
    float* sqs  = (float*)(smem + SM_SQS);
    float* part = (float*)(smem + SM_PART);

    const size_t rowbase = (size_t)blockIdx.x * MTILE;
    const float* fblk = features + rowbase * F_DIM;

    // ---- w2sum[f] = sum_e W[f,e]^2
    if (tid < F_DIM) {
        const float4* wr = (const float4*)(W + (size_t)tid * E_DIM);
        float s = 0.f;
        #pragma unroll
        for (int i = 0; i < E_DIM / 4; ++i) {
            float4 v = wr[i];
            s = fmaf(v.x, v.x, s); s = fmaf(v.y, v.y, s);
            s = fmaf(v.z, v.z, s); s = fmaf(v.w, v.w, s);
        }
        w2s[tid] = s;
    }

    // ---- zero K-pad: A cols 200..207, B rows 200..207 (hi & lo)
    {
        const int i = tid, row = i >> 1, c2 = 200 + 4 * (i & 1);
        const uint32_t oa = (uint32_t)(row * SA_B + c2 * 2);
        *(uint2*)(smem + SM_A_HI + oa) = make_uint2(0, 0);
        *(uint2*)(smem + SM_A_LO + oa) = make_uint2(0, 0);
        const int k = 200 + (i >> 5);
        const uint32_t ob = (uint32_t)(k * SB_B + (i & 31) * 4);
        *(uint32_t*)(smem + SM_B_HI + ob) = 0;
        *(uint32_t*)(smem + SM_B_LO + ob) = 0;
    }

    // ---- stage A: 128x200 fp32 -> bf16 hi/lo, row-major stride 432B
    #pragma unroll 2
    for (int i = 0; i < 12800 / THREADS; ++i) {
        const int p = tid + i * THREADS;           // pair index
        const int row = p / 100;
        const int c2 = 2 * (p - row * 100);
        const float2 x = *(const float2*)(fblk + row * F_DIM + c2);
        uint32_t hi = cvt_bf16x2(x.x, x.y);
        float h0 = __uint_as_float(hi << 16);
        float h1 = __uint_as_float(hi & 0xFFFF0000u);
        uint32_t lo = cvt_bf16x2(x.x - h0, x.y - h1);
        const uint32_t o = (uint32_t)(row * SA_B + c2 * 2);
        *(uint32_t*)(smem + SM_A_HI + o) = hi;
        *(uint32_t*)(smem + SM_A_LO + o) = lo;
    }

    // ---- stage B: W[k=f][n=e] -> k-major bf16 hi/lo, stride 144B
    #pragma unroll 2
    for (int i = 0; i < 25; ++i) {
        const int k = w + 8 * i;                   // 0..199
        const float2 x = *(const float2*)(W + (size_t)k * E_DIM + 2 * lane);
        uint32_t hi = cvt_bf16x2(x.x, x.y);
        float h0 = __uint_as_float(hi << 16);
        float h1 = __uint_as_float(hi & 0xFFFF0000u);
        uint32_t lo = cvt_bf16x2(x.x - h0, x.y - h1);
        const uint32_t o = (uint32_t)(k * SB_B + lane * 4);
        *(uint32_t*)(smem + SM_B_HI + o) = hi;
        *(uint32_t*)(smem + SM_B_LO + o) = lo;
    }
    __syncthreads();

    // ---- per-lane ldmatrix base offsets
    const int mrow = (lane & 7) + ((lane >> 3) & 1) * 8;  // row within 16
    const int mk   = (lane >> 4) & 1;                     // k-half select
    // A: matrices (rows +0..7 / +8..15) x (k-lo / k-hi)
    const uint32_t aRow = (uint32_t)((32 * mg + mrow) * SA_B + mk * 16);
    // B(trans): matrices (k +0..7 / +8..15) x (ntile j0 / j0+1)
    const uint32_t bRow = (uint32_t)(mrow * SB_B + 16 * (4 * ng + mk));
    const uint32_t aHi = sb + SM_A_HI + aRow, aLo = sb + SM_A_LO + aRow;
    const uint32_t bHi = sb + SM_B_HI + bRow, bLo = sb + SM_B_LO + bRow;

    float c[2][4][4];
    #pragma unroll
    for (int mi = 0; mi < 2; ++mi)
        #pragma unroll
        for (int j = 0; j < 4; ++j)
            #pragma unroll
            for (int q = 0; q < 4; ++q) c[mi][j][q] = 0.f;

    // ---- main loop: fully unrolled, 8 ldmatrix.x4 + 24 HMMA per k-step
    #pragma unroll
    for (int k = 0; k < NK; ++k) {
        const uint32_t ka = (uint32_t)(k * 32);        // A k advance (bytes)
        const uint32_t kb = (uint32_t)(k * 16 * SB_B); // B k advance
        uint32_t ah[2][4], al[2][4];
        ldm_x4(ah[0], aHi + ka);
        ldm_x4(ah[1], aHi + ka + 16 * SA_B);
        ldm_x4(al[0], aLo + ka);
        ldm_x4(al[1], aLo + ka + 16 * SA_B);
        #pragma unroll
        for (int jp = 0; jp < 2; ++jp) {
            uint32_t bh[4], bl[4];
            ldm_x4_t(bh, bHi + kb + jp * 32);
            ldm_x4_t(bl, bLo + kb + jp * 32);
            #pragma unroll
            for (int mi = 0; mi < 2; ++mi) {
                mma_bf16(c[mi][2 * jp],     ah[mi], bh[0], bh[1]);
                mma_bf16(c[mi][2 * jp],     ah[mi], bl[0], bl[1]);
                mma_bf16(c[mi][2 * jp],     al[mi], bh[0], bh[1]);
                mma_bf16(c[mi][2 * jp + 1], ah[mi], bh[2], bh[3]);
                mma_bf16(c[mi][2 * jp + 1], ah[mi], bl[2], bl[3]);
                mma_bf16(c[mi][2 * jp + 1], al[mi], bh[2], bh[3]);
            }
        }
    }

    // ---- sq term: exact fp32, features re-read (L2-hot from staging)
    {
        const int row = tid >> 1, half = tid & 1;
        const float*  fr = fblk + (size_t)row * F_DIM + half * 100;
        const float4* w4 = (const float4*)(w2s + half * 100);
        float s = 0.f;
        #pragma unroll 5
        for (int i = 0; i < 25; ++i) {
            float4 x = *(const float4*)(fr + 4 * i);
            float4 v = w4[i];
            s = fmaf(x.x * x.x, v.x, s); s = fmaf(x.y * x.y, v.y, s);
            s = fmaf(x.z * x.z, v.z, s); s = fmaf(x.w * x.w, v.w, s);
        }
        s += __shfl_xor_sync(0xffffffffu, s, 1);
        if (half == 0) sqs[row] = s;
    }

    // ---- epilogue: per-warp row partials (sum of squares over 32 cols)
    {
        const int g = lane >> 2, t = lane & 3;
        #pragma unroll
        for (int mi = 0; mi < 2; ++mi) {
            #pragma unroll
            for (int b = 0; b < 2; ++b) {
                float s = 0.f;
                #pragma unroll
                for (int j = 0; j < 4; ++j) {
                    const float u = c[mi][j][2 * b], v = c[mi][j][2 * b + 1];
                    s = fmaf(u, u, s);
                    s = fmaf(v, v, s);
                }
                s += __shfl_xor_sync(0xffffffffu, s, 1);
                s += __shfl_xor_sync(0xffffffffu, s, 2);
                if (t == 0)
                    part[ng * 128 + 32 * mg + 16 * mi + 8 * b + g] = s;
            }
        }
    }
    __syncthreads();

    if (tid < MTILE)
        out[rowbase + tid] = part[tid] + part[128 + tid] - sqs[tid];
}

extern "C" void kernel_launch(void* const* d_in, const int* in_sizes, int n_in,
                              void* d_out, int out_size)
{
    const float* features = (const float*)d_in[0];
    const float* W        = (const float*)d_in[1];
    if (n_in >= 2 && in_sizes[0] < in_sizes[1]) {
        features = (const float*)d_in[1];
        W        = (const float*)d_in[0];
    }
    float* out = (float*)d_out;

    cudaFuncSetAttribute(fm_mma_kernel,
                         cudaFuncAttributeMaxDynamicSharedMemorySize, SMEM_TOTAL);

    const int B = out_size;              // 16384
    const int blocks = B / MTILE;        // 128 -> single wave, 1 CTA/SM
    fm_mma_kernel<<<blocks, THREADS, SMEM_TOTAL>>>(features, W, out);
}

// round 7
// speedup vs baseline: 1.9200x; 1.3811x over previous
#include <cuda_runtime.h>
#include <cstdint>

// FM second-order term via mma.sync (HMMA) split-bf16 GEMM, K-split x2.
//   sum_emb = features @ W  (M=16384, K=200->208, N=64), 3 bf16 products
//   out[b]  = sum_e sum_emb[b,e]^2 - sum_f features[b,f]^2 * w2sum[f]
// 512 threads = 2 k-groups x 4 m-groups x 2 n-groups. Warp tile 32x32 over
// its k-half. kg1 stores partial C to smem; kg0 adds, squares, reduces.

typedef unsigned long long ull;

constexpr int F_DIM = 200;
constexpr int E_DIM = 64;
constexpr int MTILE = 128;
constexpr int THREADS = 512;

constexpr int SA_B = 432;               // A row stride bytes (216 bf16)
constexpr int SB_B = 144;               // B row stride bytes (72 bf16)
constexpr int CP_S = 68;                // cpart row stride (floats)

constexpr int SM_A_HI = 0;              // 128*432 = 55296
constexpr int SM_A_LO = 55296;
constexpr int SM_B_HI = 110592;         // 208*144 = 29952
constexpr int SM_B_LO = 140544;
constexpr int SM_CP   = 170496;         // 128*68*4 = 34816
constexpr int SM_W2S  = 205312;         // 200*4
constexpr int SM_SQS  = 206112;         // 128*4
constexpr int SM_PART = 206624;         // 2*128*4
constexpr int SMEM_TOTAL = 207648;

__device__ __forceinline__ uint32_t smem_u32(const void* p) {
    return (uint32_t)__cvta_generic_to_shared(p);
}
__device__ __forceinline__ uint32_t cvt_bf16x2(float lo, float hi) {
    uint32_t r;
    asm("cvt.rn.bf16x2.f32 %0, %1, %2;" : "=r"(r) : "f"(hi), "f"(lo));
    return r;
}
__device__ __forceinline__ void ldm_x4(uint32_t* r, uint32_t a) {
    asm volatile("ldmatrix.sync.aligned.m8n8.x4.shared.b16 {%0,%1,%2,%3}, [%4];"
                 : "=r"(r[0]), "=r"(r[1]), "=r"(r[2]), "=r"(r[3]) : "r"(a));
}
__device__ __forceinline__ void ldm_x4_t(uint32_t* r, uint32_t a) {
    asm volatile("ldmatrix.sync.aligned.m8n8.x4.trans.shared.b16 {%0,%1,%2,%3}, [%4];"
                 : "=r"(r[0]), "=r"(r[1]), "=r"(r[2]), "=r"(r[3]) : "r"(a));
}
__device__ __forceinline__ void mma_bf16(float* c, const uint32_t* a,
                                         uint32_t b0, uint32_t b1) {
    asm volatile(
        "mma.sync.aligned.m16n8k16.row.col.f32.bf16.bf16.f32 "
        "{%0,%1,%2,%3}, {%4,%5,%6,%7}, {%8,%9}, {%0,%1,%2,%3};"
        : "+f"(c[0]), "+f"(c[1]), "+f"(c[2]), "+f"(c[3])
        : "r"(a[0]), "r"(a[1]), "r"(a[2]), "r"(a[3]), "r"(b0), "r"(b1));
}

// one k-step: 8 ldmatrix + 24 HMMA ordered hh*8, hl*8, lh*8 (chain-free)
__device__ __forceinline__ void kstep(
    int k, uint32_t aHi, uint32_t aLo, uint32_t bHi, uint32_t bLo,
    float c[2][4][4])
{
    const uint32_t ka = (uint32_t)(k * 32);
    const uint32_t kb = (uint32_t)(k * 16 * SB_B);
    uint32_t ah[2][4], al[2][4], bh[2][4], bl[2][4];
    ldm_x4(ah[0], aHi + ka);
    ldm_x4(ah[1], aHi + ka + 16 * SA_B);
    ldm_x4(al[0], aLo + ka);
    ldm_x4(al[1], aLo + ka + 16 * SA_B);
    ldm_x4_t(bh[0], bHi + kb);
    ldm_x4_t(bh[1], bHi + kb + 32);
    ldm_x4_t(bl[0], bLo + kb);
    ldm_x4_t(bl[1], bLo + kb + 32);
    #pragma unroll
    for (int jp = 0; jp < 2; ++jp)
        #pragma unroll
        for (int mi = 0; mi < 2; ++mi) {
            mma_bf16(c[mi][2 * jp],     ah[mi], bh[jp][0], bh[jp][1]);
            mma_bf16(c[mi][2 * jp + 1], ah[mi], bh[jp][2], bh[jp][3]);
        }
    #pragma unroll
    for (int jp = 0; jp < 2; ++jp)
        #pragma unroll
        for (int mi = 0; mi < 2; ++mi) {
            mma_bf16(c[mi][2 * jp],     ah[mi], bl[jp][0], bl[jp][1]);
            mma_bf16(c[mi][2 * jp + 1], ah[mi], bl[jp][2], bl[jp][3]);
        }
    #pragma unroll
    for (int jp = 0; jp < 2; ++jp)
        #pragma unroll
        for (int mi = 0; mi < 2; ++mi) {
            mma_bf16(c[mi][2 * jp],     al[mi], bh[jp][0], bh[jp][1]);
            mma_bf16(c[mi][2 * jp + 1], al[mi], bh[jp][2], bh[jp][3]);
        }
}

__global__ void __launch_bounds__(THREADS, 1)
fm_mma_kernel(const float* __restrict__ features,
              const float* __restrict__ W,
              float* __restrict__ out)
{
    extern __shared__ __align__(16) char smem[];
    const uint32_t sb = smem_u32(smem);
    const int tid  = threadIdx.x;
    const int w    = tid >> 5;
    const int lane = tid & 31;
    const int kg   = w >> 3;            // k-group 0/1
    const int wl   = w & 7;
    const int mg   = wl >> 1;           // m-group 0..3
    const int ng   = wl & 1;            // n-group 0..1

    float* w2s  = (float*)(smem + SM_W2S);
    float* sqs  = (float*)(smem + SM_SQS);
    float* part = (float*)(smem + SM_PART);
    float* cp   = (float*)(smem + SM_CP);

    const size_t rowbase = (size_t)blockIdx.x * MTILE;
    const float* fblk = features + rowbase * F_DIM;

    // ---- w2sum[f] = sum_e W[f,e]^2
    if (tid < F_DIM) {
        const float4* wr = (const float4*)(W + (size_t)tid * E_DIM);
        float s = 0.f;
        #pragma unroll
        for (int i = 0; i < E_DIM / 4; ++i) {
            float4 v = wr[i];
            s = fmaf(v.x, v.x, s); s = fmaf(v.y, v.y, s);
            s = fmaf(v.z, v.z, s); s = fmaf(v.w, v.w, s);
        }
        w2s[tid] = s;
    }

    // ---- zero K-pad (A cols 200..207, B rows 200..207)
    if (tid < 256) {
        const int i = tid, row = i >> 1, c2 = 200 + 4 * (i & 1);
        const uint32_t oa = (uint32_t)(row * SA_B + c2 * 2);
        *(uint2*)(smem + SM_A_HI + oa) = make_uint2(0, 0);
        *(uint2*)(smem + SM_A_LO + oa) = make_uint2(0, 0);
        const int k = 200 + (i >> 5);
        const uint32_t ob = (uint32_t)(k * SB_B + (i & 31) * 4);
        *(uint32_t*)(smem + SM_B_HI + ob) = 0;
        *(uint32_t*)(smem + SM_B_LO + ob) = 0;
    }

    // ---- stage A: 128x200 fp32 -> bf16 hi/lo (25 pairs per thread)
    #pragma unroll 5
    for (int i = 0; i < 12800 / THREADS; ++i) {
        const int p = tid + i * THREADS;
        const int row = p / 100;
        const int c2 = 2 * (p - row * 100);
        const float2 x = *(const float2*)(fblk + row * F_DIM + c2);
        uint32_t hi = cvt_bf16x2(x.x, x.y);
        float h0 = __uint_as_float(hi << 16);
        float h1 = __uint_as_float(hi & 0xFFFF0000u);
        uint32_t lo = cvt_bf16x2(x.x - h0, x.y - h1);
        const uint32_t o = (uint32_t)(row * SA_B + c2 * 2);
        *(uint32_t*)(smem + SM_A_HI + o) = hi;
        *(uint32_t*)(smem + SM_A_LO + o) = lo;
    }

    // ---- stage B: W[k][e] -> k-major bf16 hi/lo (13 rows per warp)
    #pragma unroll
    for (int i = 0; i < 13; ++i) {
        const int k = w + 16 * i;
        if (k < F_DIM) {
            const float2 x = *(const float2*)(W + (size_t)k * E_DIM + 2 * lane);
            uint32_t hi = cvt_bf16x2(x.x, x.y);
            float h0 = __uint_as_float(hi << 16);
            float h1 = __uint_as_float(hi & 0xFFFF0000u);
            uint32_t lo = cvt_bf16x2(x.x - h0, x.y - h1);
            const uint32_t o = (uint32_t)(k * SB_B + lane * 4);
            *(uint32_t*)(smem + SM_B_HI + o) = hi;
            *(uint32_t*)(smem + SM_B_LO + o) = lo;
        }
    }
    __syncthreads();

    // ---- per-lane ldmatrix bases
    const int mrow = (lane & 7) + ((lane >> 3) & 1) * 8;
    const int mk   = (lane >> 4) & 1;
    const uint32_t aRow = (uint32_t)((32 * mg + mrow) * SA_B + mk * 16);
    const uint32_t bRow = (uint32_t)(mrow * SB_B + 16 * (4 * ng + mk));
    const uint32_t aHi = sb + SM_A_HI + aRow, aLo = sb + SM_A_LO + aRow;
    const uint32_t bHi = sb + SM_B_HI + bRow, bLo = sb + SM_B_LO + bRow;

    float c[2][4][4];
    #pragma unroll
    for (int mi = 0; mi < 2; ++mi)
        #pragma unroll
        for (int j = 0; j < 4; ++j)
            #pragma unroll
            for (int q = 0; q < 4; ++q) c[mi][j][q] = 0.f;

    // ---- MMA over this group's k-steps: kg0 = 0..5, kg1 = 6..12
    if (kg == 0) {
        #pragma unroll
        for (int k = 0; k < 6; ++k) kstep(k, aHi, aLo, bHi, bLo, c);
    } else {
        #pragma unroll
        for (int k = 6; k < 13; ++k) kstep(k, aHi, aLo, bHi, bLo, c);
    }

    // ---- sq term (threads 0..255): exact fp32, L2-hot re-read
    if (tid < 256) {
        const int row = tid >> 1, half = tid & 1;
        const float*  fr = fblk + (size_t)row * F_DIM + half * 100;
        const float4* w4 = (const float4*)(w2s + half * 100);
        float s = 0.f;
        #pragma unroll 5
        for (int i = 0; i < 25; ++i) {
            float4 x = *(const float4*)(fr + 4 * i);
            float4 v = w4[i];
            s = fmaf(x.x * x.x, v.x, s); s = fmaf(x.y * x.y, v.y, s);
            s = fmaf(x.z * x.z, v.z, s); s = fmaf(x.w * x.w, v.w, s);
        }
        s += __shfl_xor_sync(0xffffffffu, s, 1);
        if (half == 0) sqs[row] = s;
    }

    // ---- kg1 stores its partial C tile
    if (kg == 1) {
        const int R = 32 * mg + (lane >> 2);
        #pragma unroll
        for (int mi = 0; mi < 2; ++mi)
            #pragma unroll
            for (int j = 0; j < 4; ++j) {
                const int C = 32 * ng + 8 * j + 2 * (lane & 3);
                *(float2*)&cp[(R + 16 * mi) * CP_S + C] =
                    make_float2(c[mi][j][0], c[mi][j][1]);
                *(float2*)&cp[(R + 16 * mi + 8) * CP_S + C] =
                    make_float2(c[mi][j][2], c[mi][j][3]);
            }
    }
    __syncthreads();

    // ---- kg0: add kg1 partials, square, row-reduce
    if (kg == 0) {
        const int R = 32 * mg + (lane >> 2);
        #pragma unroll
        for (int mi = 0; mi < 2; ++mi)
            #pragma unroll
            for (int j = 0; j < 4; ++j) {
                const int C = 32 * ng + 8 * j + 2 * (lane & 3);
                float2 p0 = *(const float2*)&cp[(R + 16 * mi) * CP_S + C];
                float2 p1 = *(const float2*)&cp[(R + 16 * mi + 8) * CP_S + C];
                c[mi][j][0] += p0.x; c[mi][j][1] += p0.y;
                c[mi][j][2] += p1.x; c[mi][j][3] += p1.y;
            }
        const int g = lane >> 2, t = lane & 3;
        #pragma unroll
        for (int mi = 0; mi < 2; ++mi)
            #pragma unroll
            for (int b = 0; b < 2; ++b) {
                float s = 0.f;
                #pragma unroll
                for (int j = 0; j < 4; ++j) {
                    const float u = c[mi][j][2 * b], v = c[mi][j][2 * b + 1];
                    s = fmaf(u, u, s);
                    s = fmaf(v, v, s);
                }
                s += __shfl_xor_sync(0xffffffffu, s, 1);
                s += __shfl_xor_sync(0xffffffffu, s, 2);
                if (t == 0)
                    part[ng * 128 + 32 * mg + 16 * mi + 8 * b + g] = s;
            }
    }
    __syncthreads();

    if (tid < MTILE)
        out[rowbase + tid] = part[tid] + part[128 + tid] - sqs[tid];
}

extern "C" void kernel_launch(void* const* d_in, const int* in_sizes, int n_in,
                              void* d_out, int out_size)
{
    const float* features = (const float*)d_in[0];
    const float* W        = (const float*)d_in[1];
    if (n_in >= 2 && in_sizes[0] < in_sizes[1]) {
        features = (const float*)d_in[1];
        W        = (const float*)d_in[0];
    }
    float* out = (float*)d_out;

    cudaFuncSetAttribute(fm_mma_kernel,
                         cudaFuncAttributeMaxDynamicSharedMemorySize, SMEM_TOTAL);

    const int B = out_size;              // 16384
    const int blocks = B / MTILE;        // 128 -> single wave, 1 CTA/SM
    fm_mma_kernel<<<blocks, THREADS, SMEM_TOTAL>>>(features, W, out);
}